// round 4
// baseline (speedup 1.0000x reference)
#include <cuda_runtime.h>
#include <cstdint>
#include <cstddef>

// Problem constants
#define B_  16
#define C_  512
#define N_  4096
#define NH  8
#define HD  64
#define EPSF 1e-6f

// ---------------------------------------------------------------------------
// Scratch (device globals: allocation-free rule)
// ---------------------------------------------------------------------------
__device__ float g_q [B_ * C_ * N_];        // relu(q), later scaled by 1/den
__device__ float g_k [B_ * C_ * N_];        // relu(k)
__device__ float g_v [B_ * C_ * N_];        // v
__device__ float g_kv[B_ * NH * 65 * HD];   // per (b,h): [65][64]
__device__ float g_M [B_ * C_ * C_];        // folded w_o @ kv per batch

// ---------------------------------------------------------------------------
// Packed fp32x2 helpers (sm_103a FFMA2 path — 2x fp32 throughput)
// ---------------------------------------------------------------------------
__device__ __forceinline__ unsigned long long pack2(float x) {
    unsigned long long r;
    asm("mov.b64 %0, {%1, %1};" : "=l"(r) : "f"(x));
    return r;
}
__device__ __forceinline__ void ffma2(unsigned long long& d,
                                      unsigned long long a,
                                      unsigned long long b) {
    asm("fma.rn.f32x2 %0, %1, %2, %0;" : "+l"(d) : "l"(a), "l"(b));
}

// ---------------------------------------------------------------------------
// Kernel 1: fused (x+pos) elementwise + QK/V GEMM + relu
//   C[1536,4096] = W[1536,512] @ X[512,4096] per batch
//   rows [0,1024): w_qk vs (x+pos), relu -> g_q / g_k
//   rows [1024,1536): w_v vs x -> g_v
//   128x128x8 tile, 256 threads, 8x8 microtile in f32x2 pairs
// ---------------------------------------------------------------------------
__global__ __launch_bounds__(256, 2)
void k_qkv(const float* __restrict__ x, const float* __restrict__ pos,
           const float* __restrict__ w_qk, const float* __restrict__ w_v)
{
    __shared__ float As[8][128];
    __shared__ float Bs[8][128];

    const int b  = blockIdx.z;
    const int bm = blockIdx.y;   // 0..11 (8 qk blocks + 4 v blocks)
    const int bn = blockIdx.x;   // 0..31
    const int tid = threadIdx.x;
    const bool is_qk = (bm < 8);

    const float* W = is_qk ? (w_qk + (size_t)bm * 128 * 512)
                           : (w_v  + (size_t)(bm - 8) * 128 * 512);
    const float* X = x   + (size_t)b * C_ * N_ + (size_t)bn * 128;
    const float* P = pos + (size_t)b * C_ * N_ + (size_t)bn * 128;

    const int a_row = tid >> 1;          // 0..127
    const int a_k   = (tid & 1) * 4;     // 0 or 4
    const int b_k   = tid >> 5;          // 0..7
    const int b_n   = (tid & 31) * 4;    // 0..124
    const int tx = tid & 15, ty = tid >> 4;

    unsigned long long acc[8][4];
#pragma unroll
    for (int i = 0; i < 8; i++)
#pragma unroll
        for (int j = 0; j < 4; j++) acc[i][j] = 0ULL;

    for (int k0 = 0; k0 < 512; k0 += 8) {
        float4 av = *reinterpret_cast<const float4*>(W + (size_t)a_row * 512 + k0 + a_k);
        float4 bv = *reinterpret_cast<const float4*>(X + (size_t)(k0 + b_k) * N_ + b_n);
        if (is_qk) {
            float4 pv = *reinterpret_cast<const float4*>(P + (size_t)(k0 + b_k) * N_ + b_n);
            bv.x += pv.x; bv.y += pv.y; bv.z += pv.z; bv.w += pv.w;
        }
        As[a_k + 0][a_row] = av.x;
        As[a_k + 1][a_row] = av.y;
        As[a_k + 2][a_row] = av.z;
        As[a_k + 3][a_row] = av.w;
        *reinterpret_cast<float4*>(&Bs[b_k][b_n]) = bv;
        __syncthreads();

#pragma unroll
        for (int kk = 0; kk < 8; kk++) {
            float4 a0 = *reinterpret_cast<const float4*>(&As[kk][ty * 8]);
            float4 a1 = *reinterpret_cast<const float4*>(&As[kk][ty * 8 + 4]);
            const unsigned long long* bp =
                reinterpret_cast<const unsigned long long*>(&Bs[kk][tx * 8]);
            unsigned long long b0 = bp[0], b1 = bp[1], b2 = bp[2], b3 = bp[3];
            unsigned long long a2[8];
            a2[0] = pack2(a0.x); a2[1] = pack2(a0.y); a2[2] = pack2(a0.z); a2[3] = pack2(a0.w);
            a2[4] = pack2(a1.x); a2[5] = pack2(a1.y); a2[6] = pack2(a1.z); a2[7] = pack2(a1.w);
#pragma unroll
            for (int i = 0; i < 8; i++) {
                ffma2(acc[i][0], a2[i], b0);
                ffma2(acc[i][1], a2[i], b1);
                ffma2(acc[i][2], a2[i], b2);
                ffma2(acc[i][3], a2[i], b3);
            }
        }
        __syncthreads();
    }

    const int gm0 = bm * 128 + ty * 8;
    const int gn0 = bn * 128 + tx * 8;
#pragma unroll
    for (int i = 0; i < 8; i++) {
        int gm = gm0 + i;
        float* dst;
        if (gm < 512)       dst = g_q + ((size_t)b * C_ + gm       ) * N_;
        else if (gm < 1024) dst = g_k + ((size_t)b * C_ + gm -  512) * N_;
        else                dst = g_v + ((size_t)b * C_ + gm - 1024) * N_;
#pragma unroll
        for (int j = 0; j < 4; j++) {
            float2 c2 = *reinterpret_cast<float2*>(&acc[i][j]);
            if (is_qk) { c2.x = fmaxf(c2.x, 0.f); c2.y = fmaxf(c2.y, 0.f); }
            *reinterpret_cast<float2*>(dst + gn0 + 2 * j) = c2;
        }
    }
}

// ---------------------------------------------------------------------------
// Kernel 2: kv[e,d] = sum_n v_pad[e,n] * k[d,n]   per (b,h)
//   one block per (b,h): 256 threads as (16,16), n-tiles of 64
// ---------------------------------------------------------------------------
__global__ __launch_bounds__(256)
void k_kv()
{
    __shared__ float Ks[64][65];
    __shared__ float Vs[64][65];

    const int bh  = blockIdx.x;            // b*8 + h ; channel base = bh*64
    const int tid = threadIdx.x;
    const int tx = tid & 15, ty = tid >> 4;

    const float* Kg = g_k + (size_t)bh * 64 * N_;
    const float* Vg = g_v + (size_t)bh * 64 * N_;

    float acc[4][4];
    float acco[4];
#pragma unroll
    for (int i = 0; i < 4; i++) {
        acco[i] = 0.f;
#pragma unroll
        for (int j = 0; j < 4; j++) acc[i][j] = 0.f;
    }

    const int lr = tid >> 4;          // 0..15
    const int lc = (tid & 15) * 4;    // 0..60

    for (int n0 = 0; n0 < N_; n0 += 64) {
        __syncthreads();
#pragma unroll
        for (int rr = 0; rr < 4; rr++) {
            int row = lr + 16 * rr;
            float4 kq = *reinterpret_cast<const float4*>(Kg + (size_t)row * N_ + n0 + lc);
            float4 vq = *reinterpret_cast<const float4*>(Vg + (size_t)row * N_ + n0 + lc);
            Ks[row][lc + 0] = kq.x; Ks[row][lc + 1] = kq.y;
            Ks[row][lc + 2] = kq.z; Ks[row][lc + 3] = kq.w;
            Vs[row][lc + 0] = vq.x; Vs[row][lc + 1] = vq.y;
            Vs[row][lc + 2] = vq.z; Vs[row][lc + 3] = vq.w;
        }
        __syncthreads();

#pragma unroll 8
        for (int nn = 0; nn < 64; nn++) {
            float kk4[4], vv[4];
#pragma unroll
            for (int j = 0; j < 4; j++) kk4[j] = Ks[tx + 16 * j][nn];
#pragma unroll
            for (int i = 0; i < 4; i++) vv[i] = Vs[ty + 16 * i][nn];
#pragma unroll
            for (int i = 0; i < 4; i++)
#pragma unroll
                for (int j = 0; j < 4; j++) acc[i][j] += vv[i] * kk4[j];
            if (ty == 0) {
#pragma unroll
                for (int j = 0; j < 4; j++) acco[j] += kk4[j];   // ones row (e=64)
            }
        }
    }

    float* kvb = g_kv + (size_t)bh * 65 * 64;
#pragma unroll
    for (int i = 0; i < 4; i++)
#pragma unroll
        for (int j = 0; j < 4; j++)
            kvb[(ty + 16 * i) * 64 + tx + 16 * j] = acc[i][j];
    if (ty == 0) {
#pragma unroll
        for (int j = 0; j < 4; j++) kvb[64 * 64 + tx + 16 * j] = acco[j];
    }
}

// ---------------------------------------------------------------------------
// Kernel 3: fold w_o into kv:  M_b[c, h*64+d] = sum_e w_o[c, h*64+e]*kv[e,d]
//   one block per (b,h)
// ---------------------------------------------------------------------------
__global__ __launch_bounds__(256)
void k_fold(const float* __restrict__ w_o)
{
    __shared__ float kvs[64][65];
    __shared__ float ws[4][64];

    const int bh = blockIdx.x;
    const int b = bh >> 3, h = bh & 7;
    const int tid = threadIdx.x;

    for (int i = tid; i < 64 * 64; i += 256)
        kvs[i >> 6][i & 63] = g_kv[(size_t)bh * 65 * 64 + i];

    const int d  = tid & 63;
    const int cl = tid >> 6;   // 0..3

    for (int cc = 0; cc < 128; cc++) {
        __syncthreads();
        ws[tid >> 6][tid & 63] =
            w_o[(size_t)(cc * 4 + (tid >> 6)) * 512 + h * 64 + (tid & 63)];
        __syncthreads();
        float accv = 0.f;
#pragma unroll
        for (int e = 0; e < 64; e++) accv += ws[cl][e] * kvs[e][d];
        int c = cc * 4 + cl;
        g_M[((size_t)b * 512 + c) * 512 + h * 64 + d] = accv;
    }
}

// ---------------------------------------------------------------------------
// Kernel 4: denominator + scale q in place:
//   den[h,n] = sum_d kv[64,d]*q[h*64+d, n];   q <- q / (den + eps)
// ---------------------------------------------------------------------------
__global__ __launch_bounds__(256)
void k_scale()
{
    __shared__ float r[64];
    const int bh = blockIdx.x;
    const int n  = blockIdx.y * 256 + threadIdx.x;

    if (threadIdx.x < 64)
        r[threadIdx.x] = g_kv[(size_t)bh * 65 * 64 + 64 * 64 + threadIdx.x];
    __syncthreads();

    float* qcol = g_q + (size_t)bh * 64 * N_ + n;
    float qv[64];
    float den = 0.f;
#pragma unroll
    for (int dd = 0; dd < 64; dd++) {
        qv[dd] = qcol[(size_t)dd * N_];
        den += r[dd] * qv[dd];
    }
    float inv = 1.0f / (den + EPSF);
#pragma unroll
    for (int dd = 0; dd < 64; dd++)
        qcol[(size_t)dd * N_] = qv[dd] * inv;
}

// ---------------------------------------------------------------------------
// Kernel 5: final GEMM  out[b] = M_b[512,512] @ q_scaled[512,4096]
// ---------------------------------------------------------------------------
__global__ __launch_bounds__(256, 2)
void k_final(float* __restrict__ out)
{
    __shared__ float As[8][128];
    __shared__ float Bs[8][128];

    const int b  = blockIdx.z;
    const int bm = blockIdx.y;   // 0..3
    const int bn = blockIdx.x;   // 0..31
    const int tid = threadIdx.x;

    const float* W = g_M + (size_t)b * 512 * 512 + (size_t)bm * 128 * 512;
    const float* X = g_q + (size_t)b * C_ * N_ + (size_t)bn * 128;

    const int a_row = tid >> 1;
    const int a_k   = (tid & 1) * 4;
    const int b_k   = tid >> 5;
    const int b_n   = (tid & 31) * 4;
    const int tx = tid & 15, ty = tid >> 4;

    unsigned long long acc[8][4];
#pragma unroll
    for (int i = 0; i < 8; i++)
#pragma unroll
        for (int j = 0; j < 4; j++) acc[i][j] = 0ULL;

    for (int k0 = 0; k0 < 512; k0 += 8) {
        float4 av = *reinterpret_cast<const float4*>(W + (size_t)a_row * 512 + k0 + a_k);
        float4 bv = *reinterpret_cast<const float4*>(X + (size_t)(k0 + b_k) * N_ + b_n);
        As[a_k + 0][a_row] = av.x;
        As[a_k + 1][a_row] = av.y;
        As[a_k + 2][a_row] = av.z;
        As[a_k + 3][a_row] = av.w;
        *reinterpret_cast<float4*>(&Bs[b_k][b_n]) = bv;
        __syncthreads();

#pragma unroll
        for (int kk = 0; kk < 8; kk++) {
            float4 a0 = *reinterpret_cast<const float4*>(&As[kk][ty * 8]);
            float4 a1 = *reinterpret_cast<const float4*>(&As[kk][ty * 8 + 4]);
            const unsigned long long* bp =
                reinterpret_cast<const unsigned long long*>(&Bs[kk][tx * 8]);
            unsigned long long b0 = bp[0], b1 = bp[1], b2 = bp[2], b3 = bp[3];
            unsigned long long a2[8];
            a2[0] = pack2(a0.x); a2[1] = pack2(a0.y); a2[2] = pack2(a0.z); a2[3] = pack2(a0.w);
            a2[4] = pack2(a1.x); a2[5] = pack2(a1.y); a2[6] = pack2(a1.z); a2[7] = pack2(a1.w);
#pragma unroll
            for (int i = 0; i < 8; i++) {
                ffma2(acc[i][0], a2[i], b0);
                ffma2(acc[i][1], a2[i], b1);
                ffma2(acc[i][2], a2[i], b2);
                ffma2(acc[i][3], a2[i], b3);
            }
        }
        __syncthreads();
    }

    const int gm0 = bm * 128 + ty * 8;
    const int gn0 = bn * 128 + tx * 8;
#pragma unroll
    for (int i = 0; i < 8; i++) {
        float* dst = out + ((size_t)b * C_ + gm0 + i) * N_;
#pragma unroll
        for (int j = 0; j < 4; j++) {
            float2 c2 = *reinterpret_cast<float2*>(&acc[i][j]);
            *reinterpret_cast<float2*>(dst + gn0 + 2 * j) = c2;
        }
    }
}

// ---------------------------------------------------------------------------
extern "C" void kernel_launch(void* const* d_in, const int* in_sizes, int n_in,
                              void* d_out, int out_size)
{
    const float* x    = (const float*)d_in[0];
    const float* pos  = (const float*)d_in[1];
    const float* w_qk = (const float*)d_in[2];
    const float* w_v  = (const float*)d_in[3];
    const float* w_o  = (const float*)d_in[4];
    float* out = (float*)d_out;

    dim3 g1(32, 12, 16);
    k_qkv<<<g1, 256>>>(x, pos, w_qk, w_v);

    k_kv<<<B_ * NH, 256>>>();

    k_fold<<<B_ * NH, 256>>>(w_o);

    dim3 gs(B_ * NH, 16);
    k_scale<<<gs, 256>>>();

    dim3 g2(32, 4, 16);
    k_final<<<g2, 256>>>(out);
}

// round 9
// speedup vs baseline: 1.8434x; 1.8434x over previous
#include <cuda_runtime.h>
#include <cuda_bf16.h>
#include <cstdint>
#include <cstddef>

// Problem constants
#define B_  16
#define C_  512
#define N_  4096
#define NH  8
#define HD  64
#define EPSF 1e-6f

// ---------------------------------------------------------------------------
// Scratch (device globals: allocation-free rule)
// ---------------------------------------------------------------------------
__device__ float g_q [B_ * C_ * N_];        // relu(q) fp32 (consumed by k_scale)
__device__ float g_k [B_ * C_ * N_];        // relu(k)
__device__ float g_v [B_ * C_ * N_];        // v
__device__ float g_kv[B_ * NH * 65 * HD];   // per (b,h): [65][64]

// bf16 split operands
__device__ __nv_bfloat16 s_Ahi[1536 * 512]; // [w_qk ; w_v] rows, K-major
__device__ __nv_bfloat16 s_Alo[1536 * 512];
__device__ __nv_bfloat16 s_Bxp_hi[(size_t)B_ * N_ * C_];  // (x+pos)^T : [b][n][k]
__device__ __nv_bfloat16 s_Bxp_lo[(size_t)B_ * N_ * C_];
__device__ __nv_bfloat16 s_Bx_hi [(size_t)B_ * N_ * C_];  // x^T : [b][n][k]
__device__ __nv_bfloat16 s_Bx_lo [(size_t)B_ * N_ * C_];
__device__ __nv_bfloat16 s_qT_hi [(size_t)B_ * N_ * C_];  // scaled q^T : [b][n][c]
__device__ __nv_bfloat16 s_qT_lo [(size_t)B_ * N_ * C_];
__device__ __nv_bfloat16 s_Mhi[B_ * C_ * C_];             // folded w_o@kv per batch
__device__ __nv_bfloat16 s_Mlo[B_ * C_ * C_];

// ---------------------------------------------------------------------------
// mma.sync helpers (sm_80 baseline PTX — compiles at compute_103)
// ---------------------------------------------------------------------------
__device__ __forceinline__ uint32_t smem_u32(const void* p) {
    uint32_t a;
    asm("{ .reg .u64 t; cvta.to.shared.u64 t, %1; cvt.u32.u64 %0, t; }" : "=r"(a) : "l"(p));
    return a;
}
__device__ __forceinline__ void ldsm4(uint32_t* r, uint32_t addr) {
    asm volatile("ldmatrix.sync.aligned.m8n8.x4.shared.b16 {%0,%1,%2,%3}, [%4];"
                 : "=r"(r[0]), "=r"(r[1]), "=r"(r[2]), "=r"(r[3]) : "r"(addr));
}
__device__ __forceinline__ void mma16816(float* c, const uint32_t* a, const uint32_t* b) {
    asm volatile(
        "mma.sync.aligned.m16n8k16.row.col.f32.bf16.bf16.f32 "
        "{%0,%1,%2,%3}, {%4,%5,%6,%7}, {%8,%9}, {%0,%1,%2,%3};"
        : "+f"(c[0]), "+f"(c[1]), "+f"(c[2]), "+f"(c[3])
        : "r"(a[0]), "r"(a[1]), "r"(a[2]), "r"(a[3]), "r"(b[0]), "r"(b[1]));
}
__device__ __forceinline__ uint32_t pack_bf2(float a, float b) {
    __nv_bfloat16 ha = __float2bfloat16(a), hb = __float2bfloat16(b);
    return (uint32_t)__bfloat16_as_ushort(ha) |
           ((uint32_t)__bfloat16_as_ushort(hb) << 16);
}

// ---------------------------------------------------------------------------
// Kernel: weight conversion fp32 -> bf16 hi/lo  (1536x512)
// ---------------------------------------------------------------------------
__global__ void k_convw(const float* __restrict__ w_qk, const float* __restrict__ w_v)
{
    int idx = blockIdx.x * 256 + threadIdx.x;          // 0 .. 1536*512-1
    float v = (idx < 1024 * 512) ? w_qk[idx] : w_v[idx - 1024 * 512];
    __nv_bfloat16 h = __float2bfloat16(v);
    s_Ahi[idx] = h;
    s_Alo[idx] = __float2bfloat16(v - __bfloat162float(h));
}

// ---------------------------------------------------------------------------
// Kernel: transpose + convert x / (x+pos)  ->  [b][n][k] bf16 hi/lo
// ---------------------------------------------------------------------------
__global__ __launch_bounds__(256)
void k_prep(const float* __restrict__ x, const float* __restrict__ pos)
{
    __shared__ float sx[32][33];
    __shared__ float sp[32][33];
    const int b  = blockIdx.z;
    const int k0 = blockIdx.y * 32;
    const int n0 = blockIdx.x * 32;
    const int c  = threadIdx.x & 31;
    const int r0 = threadIdx.x >> 5;   // 0..7

#pragma unroll
    for (int i = 0; i < 4; i++) {
        int r = r0 + 8 * i;
        size_t off = ((size_t)b * C_ + k0 + r) * N_ + n0 + c;
        float xv = x[off];
        sx[r][c] = xv;
        sp[r][c] = xv + pos[off];
    }
    __syncthreads();
#pragma unroll
    for (int i = 0; i < 4; i++) {
        int r = r0 + 8 * i;                       // n within tile
        float vx = sx[c][r];
        float vp = sp[c][r];
        size_t o = ((size_t)b * N_ + n0 + r) * C_ + k0 + c;
        __nv_bfloat16 hp = __float2bfloat16(vp);
        __nv_bfloat16 hx = __float2bfloat16(vx);
        s_Bxp_hi[o] = hp;
        s_Bxp_lo[o] = __float2bfloat16(vp - __bfloat162float(hp));
        s_Bx_hi[o]  = hx;
        s_Bx_lo[o]  = __float2bfloat16(vx - __bfloat162float(hx));
    }
}

// ---------------------------------------------------------------------------
// HMMA GEMM (bf16x3 emulated fp32): D[m][n] = sum_k A[m][k] * B[n][k]
//   Block tile 128x128, K-chunk 64, 8 warps (warp tile 32x64).
//   MODE 0: QKV  — A = s_Ahi/lo (1536 rows), B = Bxp (bm<8) or Bx,
//                  out -> g_q/g_k/g_v (relu on q,k)
//   MODE 1: final — A = s_Mhi/lo per batch, B = s_qT, out -> d_out
// grid: (bm, bn, b); block 256 threads.
// ---------------------------------------------------------------------------
#define TSTRIDE 72                 // smem row stride (elems), conflict-free for ldmatrix
#define TILE_BYTES_SM (128 * TSTRIDE * 2)
#define GSMEM_BYTES (4 * TILE_BYTES_SM)

template <int MODE>
__global__ __launch_bounds__(256)
void k_gemm(float* __restrict__ out)
{
    extern __shared__ __nv_bfloat16 smem[];   // 4 tiles: Ahi, Alo, Bhi, Blo
    const int tid = threadIdx.x;
    const int lane = tid & 31;
    const int wid  = tid >> 5;
    const int warp_m = wid & 3;          // 0..3  (m-tile of 32)
    const int warp_n = wid >> 2;         // 0..1  (n-tile of 64)
    const int bm = blockIdx.x, bn = blockIdx.y, b = blockIdx.z;

    // operand base pointers (row-major [rows][512])
    const __nv_bfloat16 *pAhi, *pAlo, *pBhi, *pBlo;
    if (MODE == 0) {
        pAhi = s_Ahi + (size_t)bm * 128 * 512;
        pAlo = s_Alo + (size_t)bm * 128 * 512;
        size_t bo = ((size_t)b * N_ + (size_t)bn * 128) * 512;
        if (bm < 8) { pBhi = s_Bxp_hi + bo; pBlo = s_Bxp_lo + bo; }
        else        { pBhi = s_Bx_hi  + bo; pBlo = s_Bx_lo  + bo; }
    } else {
        pAhi = s_Mhi + ((size_t)b * 512 + (size_t)bm * 128) * 512;
        pAlo = s_Mlo + ((size_t)b * 512 + (size_t)bm * 128) * 512;
        size_t bo = ((size_t)b * N_ + (size_t)bn * 128) * 512;
        pBhi = s_qT_hi + bo;
        pBlo = s_qT_lo + bo;
    }
    const __nv_bfloat16* srcs[4] = { pAhi, pAlo, pBhi, pBlo };

    const uint32_t sb = smem_u32(smem);
    const uint32_t sAhi = sb;
    const uint32_t sAlo = sb + TILE_BYTES_SM;
    const uint32_t sBhi = sb + 2 * TILE_BYTES_SM;
    const uint32_t sBlo = sb + 3 * TILE_BYTES_SM;

    // ldmatrix per-lane address components
    const uint32_t a_row   = warp_m * 32 + (lane & 15);       // + mi*16
    const uint32_t a_csel  = (lane >> 4) * 8;                 // k half
    const uint32_t b_row   = warp_n * 64 + (lane & 7) + ((lane >> 4) & 1) * 8; // + nj*16
    const uint32_t b_csel  = ((lane >> 3) & 1) * 8;

    float acc[2][8][4];
#pragma unroll
    for (int i = 0; i < 2; i++)
#pragma unroll
        for (int j = 0; j < 8; j++)
#pragma unroll
            for (int r = 0; r < 4; r++) acc[i][j][r] = 0.f;

    for (int kc = 0; kc < 8; kc++) {
        __syncthreads();
        // ---- load 4 x (128x64) bf16 tiles into smem (row stride 72) ----
#pragma unroll
        for (int buf = 0; buf < 4; buf++) {
            const __nv_bfloat16* bp = srcs[buf] + kc * 64;
            __nv_bfloat16* tile = smem + buf * (128 * TSTRIDE);
#pragma unroll
            for (int it = 0; it < 4; it++) {
                int u = it * 256 + tid;          // 0..1023
                int row = u >> 3, c8 = u & 7;    // col = c8*8
                uint4 v = *reinterpret_cast<const uint4*>(bp + (size_t)row * 512 + c8 * 8);
                *reinterpret_cast<uint4*>(tile + row * TSTRIDE + c8 * 8) = v;
            }
        }
        __syncthreads();

        // ---- 4 K-steps of 16 ----
#pragma unroll
        for (int ks = 0; ks < 4; ks++) {
            const uint32_t kcol = ks * 16;
            uint32_t ah[2][4], al[2][4];
#pragma unroll
            for (int mi = 0; mi < 2; mi++) {
                uint32_t ro = (a_row + mi * 16) * TSTRIDE + kcol + a_csel;
                ldsm4(ah[mi], sAhi + ro * 2);
                ldsm4(al[mi], sAlo + ro * 2);
            }
            uint32_t bh[4][4], bl[4][4];       // each covers n-tiles 2nj, 2nj+1
#pragma unroll
            for (int nj = 0; nj < 4; nj++) {
                uint32_t ro = (b_row + nj * 16) * TSTRIDE + kcol + b_csel;
                ldsm4(bh[nj], sBhi + ro * 2);
                ldsm4(bl[nj], sBlo + ro * 2);
            }
#pragma unroll
            for (int mi = 0; mi < 2; mi++)
#pragma unroll
                for (int nj = 0; nj < 4; nj++) {
                    mma16816(acc[mi][2 * nj    ], ah[mi], &bh[nj][0]);
                    mma16816(acc[mi][2 * nj + 1], ah[mi], &bh[nj][2]);
                    mma16816(acc[mi][2 * nj    ], ah[mi], &bl[nj][0]);
                    mma16816(acc[mi][2 * nj + 1], ah[mi], &bl[nj][2]);
                    mma16816(acc[mi][2 * nj    ], al[mi], &bh[nj][0]);
                    mma16816(acc[mi][2 * nj + 1], al[mi], &bh[nj][2]);
                }
        }
    }

    // ---- epilogue ----
    float* base;
    int roff;
    bool relu = false;
    if (MODE == 0) {
        if (bm < 4)      { base = g_q; roff = bm * 128;        relu = true; }
        else if (bm < 8) { base = g_k; roff = (bm - 4) * 128;  relu = true; }
        else             { base = g_v; roff = (bm - 8) * 128; }
        base += (size_t)b * C_ * N_;
    } else {
        base = out + (size_t)b * C_ * N_;
        roff = bm * 128;
    }

    const int mrow0 = roff + warp_m * 32 + (lane >> 2);
    const int ncol0 = bn * 128 + warp_n * 64 + (lane & 3) * 2;
#pragma unroll
    for (int mi = 0; mi < 2; mi++) {
#pragma unroll
        for (int nj = 0; nj < 8; nj++) {
            int cc = ncol0 + nj * 8;
            float2 v0 = make_float2(acc[mi][nj][0], acc[mi][nj][1]);
            float2 v1 = make_float2(acc[mi][nj][2], acc[mi][nj][3]);
            if (relu) {
                v0.x = fmaxf(v0.x, 0.f); v0.y = fmaxf(v0.y, 0.f);
                v1.x = fmaxf(v1.x, 0.f); v1.y = fmaxf(v1.y, 0.f);
            }
            *reinterpret_cast<float2*>(base + (size_t)(mrow0 + mi * 16    ) * N_ + cc) = v0;
            *reinterpret_cast<float2*>(base + (size_t)(mrow0 + mi * 16 + 8) * N_ + cc) = v1;
        }
    }
}

// ---------------------------------------------------------------------------
// Kernel: kv[e,d] = sum_n v_pad[e,n] * k[d,n]   per (b,h)
// ---------------------------------------------------------------------------
__global__ __launch_bounds__(256)
void k_kv()
{
    __shared__ float Ks[64][65];
    __shared__ float Vs[64][65];

    const int bh  = blockIdx.x;
    const int tid = threadIdx.x;
    const int tx = tid & 15, ty = tid >> 4;

    const float* Kg = g_k + (size_t)bh * 64 * N_;
    const float* Vg = g_v + (size_t)bh * 64 * N_;

    float acc[4][4];
    float acco[4];
#pragma unroll
    for (int i = 0; i < 4; i++) {
        acco[i] = 0.f;
#pragma unroll
        for (int j = 0; j < 4; j++) acc[i][j] = 0.f;
    }

    const int lr = tid >> 4;
    const int lc = (tid & 15) * 4;

    for (int n0 = 0; n0 < N_; n0 += 64) {
        __syncthreads();
#pragma unroll
        for (int rr = 0; rr < 4; rr++) {
            int row = lr + 16 * rr;
            float4 kq = *reinterpret_cast<const float4*>(Kg + (size_t)row * N_ + n0 + lc);
            float4 vq = *reinterpret_cast<const float4*>(Vg + (size_t)row * N_ + n0 + lc);
            Ks[row][lc + 0] = kq.x; Ks[row][lc + 1] = kq.y;
            Ks[row][lc + 2] = kq.z; Ks[row][lc + 3] = kq.w;
            Vs[row][lc + 0] = vq.x; Vs[row][lc + 1] = vq.y;
            Vs[row][lc + 2] = vq.z; Vs[row][lc + 3] = vq.w;
        }
        __syncthreads();

#pragma unroll 8
        for (int nn = 0; nn < 64; nn++) {
            float kk4[4], vv[4];
#pragma unroll
            for (int j = 0; j < 4; j++) kk4[j] = Ks[tx + 16 * j][nn];
#pragma unroll
            for (int i = 0; i < 4; i++) vv[i] = Vs[ty + 16 * i][nn];
#pragma unroll
            for (int i = 0; i < 4; i++)
#pragma unroll
                for (int j = 0; j < 4; j++) acc[i][j] += vv[i] * kk4[j];
            if (ty == 0) {
#pragma unroll
                for (int j = 0; j < 4; j++) acco[j] += kk4[j];
            }
        }
    }

    float* kvb = g_kv + (size_t)bh * 65 * 64;
#pragma unroll
    for (int i = 0; i < 4; i++)
#pragma unroll
        for (int j = 0; j < 4; j++)
            kvb[(ty + 16 * i) * 64 + tx + 16 * j] = acc[i][j];
    if (ty == 0) {
#pragma unroll
        for (int j = 0; j < 4; j++) kvb[64 * 64 + tx + 16 * j] = acco[j];
    }
}

// ---------------------------------------------------------------------------
// Kernel: fold w_o into kv -> bf16 hi/lo M matrices
//   M_b[c, h*64+d] = sum_e w_o[c, h*64+e] * kv[e,d]
// ---------------------------------------------------------------------------
__global__ __launch_bounds__(256)
void k_fold(const float* __restrict__ w_o)
{
    __shared__ float kvs[64][65];
    __shared__ float ws[4][64];

    const int bh = blockIdx.x;
    const int b = bh >> 3, h = bh & 7;
    const int tid = threadIdx.x;

    for (int i = tid; i < 64 * 64; i += 256)
        kvs[i >> 6][i & 63] = g_kv[(size_t)bh * 65 * 64 + i];

    const int d  = tid & 63;
    const int cl = tid >> 6;

    for (int cc = 0; cc < 128; cc++) {
        __syncthreads();
        ws[tid >> 6][tid & 63] =
            w_o[(size_t)(cc * 4 + (tid >> 6)) * 512 + h * 64 + (tid & 63)];
        __syncthreads();
        float accv = 0.f;
#pragma unroll
        for (int e = 0; e < 64; e++) accv += ws[cl][e] * kvs[e][d];
        int c = cc * 4 + cl;
        size_t idx = ((size_t)b * 512 + c) * 512 + h * 64 + d;
        __nv_bfloat16 hi = __float2bfloat16(accv);
        s_Mhi[idx] = hi;
        s_Mlo[idx] = __float2bfloat16(accv - __bfloat162float(hi));
    }
}

// ---------------------------------------------------------------------------
// Kernel: denominator + scaled q^T in bf16 hi/lo:
//   den[h,n] = sum_d kv[64,d]*q[h*64+d, n];  qT[b][n][h*64+d] = q/(den+eps)
// ---------------------------------------------------------------------------
__global__ __launch_bounds__(256)
void k_scale()
{
    __shared__ float r[64];
    const int bh = blockIdx.x;
    const int n  = blockIdx.y * 256 + threadIdx.x;

    if (threadIdx.x < 64)
        r[threadIdx.x] = g_kv[(size_t)bh * 65 * 64 + 64 * 64 + threadIdx.x];
    __syncthreads();

    const float* qcol = g_q + (size_t)bh * 64 * N_ + n;
    float qv[64];
    float den = 0.f;
#pragma unroll
    for (int dd = 0; dd < 64; dd++) {
        qv[dd] = qcol[(size_t)dd * N_];
        den += r[dd] * qv[dd];
    }
    const float inv = 1.0f / (den + EPSF);

    const int b = bh >> 3, h = bh & 7;
    const size_t o = ((size_t)b * N_ + n) * C_ + h * 64;

#pragma unroll
    for (int g = 0; g < 8; g++) {
        uint32_t hw[4], lw[4];
#pragma unroll
        for (int j = 0; j < 4; j++) {
            float v0 = qv[g * 8 + 2 * j] * inv;
            float v1 = qv[g * 8 + 2 * j + 1] * inv;
            __nv_bfloat16 h0 = __float2bfloat16(v0);
            __nv_bfloat16 h1 = __float2bfloat16(v1);
            hw[j] = (uint32_t)__bfloat16_as_ushort(h0) |
                    ((uint32_t)__bfloat16_as_ushort(h1) << 16);
            lw[j] = pack_bf2(v0 - __bfloat162float(h0), v1 - __bfloat162float(h1));
        }
        *reinterpret_cast<uint4*>(s_qT_hi + o + g * 8) = make_uint4(hw[0], hw[1], hw[2], hw[3]);
        *reinterpret_cast<uint4*>(s_qT_lo + o + g * 8) = make_uint4(lw[0], lw[1], lw[2], lw[3]);
    }
}

// ---------------------------------------------------------------------------
extern "C" void kernel_launch(void* const* d_in, const int* in_sizes, int n_in,
                              void* d_out, int out_size)
{
    const float* x    = (const float*)d_in[0];
    const float* pos  = (const float*)d_in[1];
    const float* w_qk = (const float*)d_in[2];
    const float* w_v  = (const float*)d_in[3];
    const float* w_o  = (const float*)d_in[4];
    float* out = (float*)d_out;

    cudaFuncSetAttribute(k_gemm<0>, cudaFuncAttributeMaxDynamicSharedMemorySize, GSMEM_BYTES);
    cudaFuncSetAttribute(k_gemm<1>, cudaFuncAttributeMaxDynamicSharedMemorySize, GSMEM_BYTES);

    k_convw<<<(1536 * 512) / 256, 256>>>(w_qk, w_v);

    dim3 gp(N_ / 32, C_ / 32, B_);
    k_prep<<<gp, 256>>>(x, pos);

    dim3 g0(12, 32, B_);                       // (bm, bn, b)
    k_gemm<0><<<g0, 256, GSMEM_BYTES>>>(nullptr);

    k_kv<<<B_ * NH, 256>>>();

    k_fold<<<B_ * NH, 256>>>(w_o);

    dim3 gs(B_ * NH, 16);
    k_scale<<<gs, 256>>>();

    dim3 g1(4, 32, B_);
    k_gemm<1><<<g1, 256, GSMEM_BYTES>>>(out);
}

// round 12
// speedup vs baseline: 2.2361x; 1.2131x over previous
#include <cuda_runtime.h>
#include <cuda_bf16.h>
#include <cstdint>
#include <cstddef>

// Problem constants
#define B_  16
#define C_  512
#define N_  4096
#define NH  8
#define HD  64
#define EPSF 1e-6f
#define NSPLIT 8

// ---------------------------------------------------------------------------
// Scratch (device globals: allocation-free rule)
// ---------------------------------------------------------------------------
__device__ float g_q [B_ * C_ * N_];        // relu(q) fp32 (consumed by k_scale)
__device__ float g_k [B_ * C_ * N_];        // relu(k)
__device__ float g_v [B_ * C_ * N_];        // v
__device__ float g_kv [B_ * NH * 65 * HD];           // per (b,h): [65][64]
__device__ float g_kvp[B_ * NH * NSPLIT * 65 * HD];  // split-N partials

// bf16 split operands
__device__ __nv_bfloat16 s_Ahi[1536 * 512]; // [w_qk ; w_v] rows, K-major
__device__ __nv_bfloat16 s_Alo[1536 * 512];
__device__ __nv_bfloat16 s_Bxp_hi[(size_t)B_ * N_ * C_];  // (x+pos)^T : [b][n][k]
__device__ __nv_bfloat16 s_Bxp_lo[(size_t)B_ * N_ * C_];
__device__ __nv_bfloat16 s_Bx_hi [(size_t)B_ * N_ * C_];  // x^T : [b][n][k]
__device__ __nv_bfloat16 s_Bx_lo [(size_t)B_ * N_ * C_];
__device__ __nv_bfloat16 s_qT_hi [(size_t)B_ * N_ * C_];  // scaled q^T : [b][n][c]
__device__ __nv_bfloat16 s_qT_lo [(size_t)B_ * N_ * C_];
__device__ __nv_bfloat16 s_Mhi[B_ * C_ * C_];             // folded w_o@kv per batch
__device__ __nv_bfloat16 s_Mlo[B_ * C_ * C_];

// ---------------------------------------------------------------------------
// mma.sync + cp.async helpers (sm_80 baseline PTX — compiles at compute_103)
// ---------------------------------------------------------------------------
__device__ __forceinline__ uint32_t smem_u32(const void* p) {
    uint32_t a;
    asm("{ .reg .u64 t; cvta.to.shared.u64 t, %1; cvt.u32.u64 %0, t; }" : "=r"(a) : "l"(p));
    return a;
}
__device__ __forceinline__ void ldsm4(uint32_t* r, uint32_t addr) {
    asm volatile("ldmatrix.sync.aligned.m8n8.x4.shared.b16 {%0,%1,%2,%3}, [%4];"
                 : "=r"(r[0]), "=r"(r[1]), "=r"(r[2]), "=r"(r[3]) : "r"(addr));
}
__device__ __forceinline__ void mma16816(float* c, const uint32_t* a, const uint32_t* b) {
    asm volatile(
        "mma.sync.aligned.m16n8k16.row.col.f32.bf16.bf16.f32 "
        "{%0,%1,%2,%3}, {%4,%5,%6,%7}, {%8,%9}, {%0,%1,%2,%3};"
        : "+f"(c[0]), "+f"(c[1]), "+f"(c[2]), "+f"(c[3])
        : "r"(a[0]), "r"(a[1]), "r"(a[2]), "r"(a[3]), "r"(b[0]), "r"(b[1]));
}
__device__ __forceinline__ void cp_async16(uint32_t saddr, const void* gptr) {
    asm volatile("cp.async.cg.shared.global [%0], [%1], 16;"
                 :: "r"(saddr), "l"(gptr) : "memory");
}
#define CP_COMMIT()  asm volatile("cp.async.commit_group;" ::: "memory")
#define CP_WAIT(nn)  asm volatile("cp.async.wait_group %0;" :: "n"(nn) : "memory")

__device__ __forceinline__ uint32_t pack_bf2(float a, float b) {
    __nv_bfloat16 ha = __float2bfloat16(a), hb = __float2bfloat16(b);
    return (uint32_t)__bfloat16_as_ushort(ha) |
           ((uint32_t)__bfloat16_as_ushort(hb) << 16);
}

// ---------------------------------------------------------------------------
// Kernel: weight conversion fp32 -> bf16 hi/lo  (1536x512)
// ---------------------------------------------------------------------------
__global__ void k_convw(const float* __restrict__ w_qk, const float* __restrict__ w_v)
{
    int idx = blockIdx.x * 256 + threadIdx.x;          // 0 .. 1536*512-1
    float v = (idx < 1024 * 512) ? w_qk[idx] : w_v[idx - 1024 * 512];
    __nv_bfloat16 h = __float2bfloat16(v);
    s_Ahi[idx] = h;
    s_Alo[idx] = __float2bfloat16(v - __bfloat162float(h));
}

// ---------------------------------------------------------------------------
// Kernel: transpose + convert x / (x+pos)  ->  [b][n][k] bf16 hi/lo
// ---------------------------------------------------------------------------
__global__ __launch_bounds__(256)
void k_prep(const float* __restrict__ x, const float* __restrict__ pos)
{
    __shared__ float sx[32][33];
    __shared__ float sp[32][33];
    const int b  = blockIdx.z;
    const int k0 = blockIdx.y * 32;
    const int n0 = blockIdx.x * 32;
    const int c  = threadIdx.x & 31;
    const int r0 = threadIdx.x >> 5;   // 0..7

#pragma unroll
    for (int i = 0; i < 4; i++) {
        int r = r0 + 8 * i;
        size_t off = ((size_t)b * C_ + k0 + r) * N_ + n0 + c;
        float xv = x[off];
        sx[r][c] = xv;
        sp[r][c] = xv + pos[off];
    }
    __syncthreads();
#pragma unroll
    for (int i = 0; i < 4; i++) {
        int r = r0 + 8 * i;                       // n within tile
        float vx = sx[c][r];
        float vp = sp[c][r];
        size_t o = ((size_t)b * N_ + n0 + r) * C_ + k0 + c;
        __nv_bfloat16 hp = __float2bfloat16(vp);
        __nv_bfloat16 hx = __float2bfloat16(vx);
        s_Bxp_hi[o] = hp;
        s_Bxp_lo[o] = __float2bfloat16(vp - __bfloat162float(hp));
        s_Bx_hi[o]  = hx;
        s_Bx_lo[o]  = __float2bfloat16(vx - __bfloat162float(hx));
    }
}

// ---------------------------------------------------------------------------
// HMMA GEMM (bf16x3 emulated fp32): D[m][n] = sum_k A[m][k] * B[n][k]
//   Block tile 128x128, K-chunk 64, 8 warps (warp tile 32x64),
//   cp.async double-buffered over K-chunks.
//   MODE 0: QKV  — A = s_Ahi/lo (1536 rows), B = Bxp (bm<8) or Bx,
//                  out -> g_q/g_k/g_v (relu on q,k)
//   MODE 1: final — A = s_Mhi/lo per batch, B = s_qT, out -> d_out
// grid: (bm, bn, b); block 256 threads.
// ---------------------------------------------------------------------------
#define TSTRIDE 72                 // smem row stride (elems), conflict-free for ldmatrix
#define TILE_BYTES_SM (128 * TSTRIDE * 2)       // 18432
#define BUF_BYTES (4 * TILE_BYTES_SM)           // 73728
#define GSMEM_BYTES (2 * BUF_BYTES)             // 147456

__device__ __forceinline__ void issue_chunk(const __nv_bfloat16* const* srcs,
                                            int kc, uint32_t sbase, int tid)
{
#pragma unroll
    for (int buf = 0; buf < 4; buf++) {
        const __nv_bfloat16* bp = srcs[buf] + kc * 64;
        uint32_t tbase = sbase + buf * TILE_BYTES_SM;
#pragma unroll
        for (int it = 0; it < 4; it++) {
            int u = it * 256 + tid;          // 0..1023
            int row = u >> 3, c8 = u & 7;    // col = c8*8
            cp_async16(tbase + (uint32_t)(row * TSTRIDE + c8 * 8) * 2,
                       bp + (size_t)row * 512 + c8 * 8);
        }
    }
}

template <int MODE>
__global__ __launch_bounds__(256)
void k_gemm(float* __restrict__ out)
{
    extern __shared__ __nv_bfloat16 smem[];   // 2 buffers x 4 tiles
    const int tid = threadIdx.x;
    const int lane = tid & 31;
    const int wid  = tid >> 5;
    const int warp_m = wid & 3;          // 0..3  (m-tile of 32)
    const int warp_n = wid >> 2;         // 0..1  (n-tile of 64)
    const int bm = blockIdx.x, bn = blockIdx.y, b = blockIdx.z;

    // operand base pointers (row-major [rows][512])
    const __nv_bfloat16 *pAhi, *pAlo, *pBhi, *pBlo;
    if (MODE == 0) {
        pAhi = s_Ahi + (size_t)bm * 128 * 512;
        pAlo = s_Alo + (size_t)bm * 128 * 512;
        size_t bo = ((size_t)b * N_ + (size_t)bn * 128) * 512;
        if (bm < 8) { pBhi = s_Bxp_hi + bo; pBlo = s_Bxp_lo + bo; }
        else        { pBhi = s_Bx_hi  + bo; pBlo = s_Bx_lo  + bo; }
    } else {
        pAhi = s_Mhi + ((size_t)b * 512 + (size_t)bm * 128) * 512;
        pAlo = s_Mlo + ((size_t)b * 512 + (size_t)bm * 128) * 512;
        size_t bo = ((size_t)b * N_ + (size_t)bn * 128) * 512;
        pBhi = s_qT_hi + bo;
        pBlo = s_qT_lo + bo;
    }
    const __nv_bfloat16* srcs[4] = { pAhi, pAlo, pBhi, pBlo };

    const uint32_t sb = smem_u32(smem);

    // ldmatrix per-lane address components
    const uint32_t a_row   = warp_m * 32 + (lane & 15);       // + mi*16
    const uint32_t a_csel  = (lane >> 4) * 8;                 // k half
    const uint32_t b_row   = warp_n * 64 + (lane & 7) + ((lane >> 4) & 1) * 8; // + nj*16
    const uint32_t b_csel  = ((lane >> 3) & 1) * 8;

    float acc[2][8][4];
#pragma unroll
    for (int i = 0; i < 2; i++)
#pragma unroll
        for (int j = 0; j < 8; j++)
#pragma unroll
            for (int r = 0; r < 4; r++) acc[i][j][r] = 0.f;

    // prologue: prefetch chunk 0
    issue_chunk(srcs, 0, sb, tid);
    CP_COMMIT();

    for (int kc = 0; kc < 8; kc++) {
        // prefetch next chunk into alternate buffer
        if (kc + 1 < 8) {
            issue_chunk(srcs, kc + 1, sb + ((kc + 1) & 1) * BUF_BYTES, tid);
            CP_COMMIT();
            CP_WAIT(1);
        } else {
            CP_WAIT(0);
        }
        __syncthreads();

        const uint32_t cbase = sb + (kc & 1) * BUF_BYTES;
        const uint32_t sAhi = cbase;
        const uint32_t sAlo = cbase + TILE_BYTES_SM;
        const uint32_t sBhi = cbase + 2 * TILE_BYTES_SM;
        const uint32_t sBlo = cbase + 3 * TILE_BYTES_SM;

        // ---- 4 K-steps of 16 ----
#pragma unroll
        for (int ks = 0; ks < 4; ks++) {
            const uint32_t kcol = ks * 16;
            uint32_t ah[2][4], al[2][4];
#pragma unroll
            for (int mi = 0; mi < 2; mi++) {
                uint32_t ro = (a_row + mi * 16) * TSTRIDE + kcol + a_csel;
                ldsm4(ah[mi], sAhi + ro * 2);
                ldsm4(al[mi], sAlo + ro * 2);
            }
            uint32_t bh[4][4], bl[4][4];       // each covers n-tiles 2nj, 2nj+1
#pragma unroll
            for (int nj = 0; nj < 4; nj++) {
                uint32_t ro = (b_row + nj * 16) * TSTRIDE + kcol + b_csel;
                ldsm4(bh[nj], sBhi + ro * 2);
                ldsm4(bl[nj], sBlo + ro * 2);
            }
#pragma unroll
            for (int mi = 0; mi < 2; mi++)
#pragma unroll
                for (int nj = 0; nj < 4; nj++) {
                    mma16816(acc[mi][2 * nj    ], ah[mi], &bh[nj][0]);
                    mma16816(acc[mi][2 * nj + 1], ah[mi], &bh[nj][2]);
                    mma16816(acc[mi][2 * nj    ], ah[mi], &bl[nj][0]);
                    mma16816(acc[mi][2 * nj + 1], ah[mi], &bl[nj][2]);
                    mma16816(acc[mi][2 * nj    ], al[mi], &bh[nj][0]);
                    mma16816(acc[mi][2 * nj + 1], al[mi], &bh[nj][2]);
                }
        }
        __syncthreads();   // tile consumed — safe for the prefetch after next
    }

    // ---- epilogue ----
    float* base;
    int roff;
    bool relu = false;
    if (MODE == 0) {
        if (bm < 4)      { base = g_q; roff = bm * 128;        relu = true; }
        else if (bm < 8) { base = g_k; roff = (bm - 4) * 128;  relu = true; }
        else             { base = g_v; roff = (bm - 8) * 128; }
        base += (size_t)b * C_ * N_;
    } else {
        base = out + (size_t)b * C_ * N_;
        roff = bm * 128;
    }

    const int mrow0 = roff + warp_m * 32 + (lane >> 2);
    const int ncol0 = bn * 128 + warp_n * 64 + (lane & 3) * 2;
#pragma unroll
    for (int mi = 0; mi < 2; mi++) {
#pragma unroll
        for (int nj = 0; nj < 8; nj++) {
            int cc = ncol0 + nj * 8;
            float2 v0 = make_float2(acc[mi][nj][0], acc[mi][nj][1]);
            float2 v1 = make_float2(acc[mi][nj][2], acc[mi][nj][3]);
            if (relu) {
                v0.x = fmaxf(v0.x, 0.f); v0.y = fmaxf(v0.y, 0.f);
                v1.x = fmaxf(v1.x, 0.f); v1.y = fmaxf(v1.y, 0.f);
            }
            *reinterpret_cast<float2*>(base + (size_t)(mrow0 + mi * 16    ) * N_ + cc) = v0;
            *reinterpret_cast<float2*>(base + (size_t)(mrow0 + mi * 16 + 8) * N_ + cc) = v1;
        }
    }
}

// ---------------------------------------------------------------------------
// Kernel: split-N partial KV: kvp[bh][ns][e][d] = sum_{n in slice} v_pad[e,n]*k[d,n]
//   grid (128, NSPLIT); block 256 as (16,16)
// ---------------------------------------------------------------------------
__global__ __launch_bounds__(256)
void k_kvp()
{
    __shared__ float Ks[64][65];
    __shared__ float Vs[64][65];

    const int bh  = blockIdx.x;
    const int ns  = blockIdx.y;
    const int tid = threadIdx.x;
    const int tx = tid & 15, ty = tid >> 4;

    const float* Kg = g_k + (size_t)bh * 64 * N_;
    const float* Vg = g_v + (size_t)bh * 64 * N_;

    float acc[4][4];
    float acco[4];
#pragma unroll
    for (int i = 0; i < 4; i++) {
        acco[i] = 0.f;
#pragma unroll
        for (int j = 0; j < 4; j++) acc[i][j] = 0.f;
    }

    const int lr = tid >> 4;
    const int lc = (tid & 15) * 4;
    const int nbeg = ns * (N_ / NSPLIT);
    const int nend = nbeg + (N_ / NSPLIT);

    for (int n0 = nbeg; n0 < nend; n0 += 64) {
        __syncthreads();
#pragma unroll
        for (int rr = 0; rr < 4; rr++) {
            int row = lr + 16 * rr;
            float4 kq = *reinterpret_cast<const float4*>(Kg + (size_t)row * N_ + n0 + lc);
            float4 vq = *reinterpret_cast<const float4*>(Vg + (size_t)row * N_ + n0 + lc);
            Ks[row][lc + 0] = kq.x; Ks[row][lc + 1] = kq.y;
            Ks[row][lc + 2] = kq.z; Ks[row][lc + 3] = kq.w;
            Vs[row][lc + 0] = vq.x; Vs[row][lc + 1] = vq.y;
            Vs[row][lc + 2] = vq.z; Vs[row][lc + 3] = vq.w;
        }
        __syncthreads();

#pragma unroll 8
        for (int nn = 0; nn < 64; nn++) {
            float kk4[4], vv[4];
#pragma unroll
            for (int j = 0; j < 4; j++) kk4[j] = Ks[tx + 16 * j][nn];
#pragma unroll
            for (int i = 0; i < 4; i++) vv[i] = Vs[ty + 16 * i][nn];
#pragma unroll
            for (int i = 0; i < 4; i++)
#pragma unroll
                for (int j = 0; j < 4; j++) acc[i][j] += vv[i] * kk4[j];
            if (ty == 0) {
#pragma unroll
                for (int j = 0; j < 4; j++) acco[j] += kk4[j];
            }
        }
    }

    float* kvb = g_kvp + ((size_t)bh * NSPLIT + ns) * 65 * 64;
#pragma unroll
    for (int i = 0; i < 4; i++)
#pragma unroll
        for (int j = 0; j < 4; j++)
            kvb[(ty + 16 * i) * 64 + tx + 16 * j] = acc[i][j];
    if (ty == 0) {
#pragma unroll
        for (int j = 0; j < 4; j++) kvb[64 * 64 + tx + 16 * j] = acco[j];
    }
}

// ---------------------------------------------------------------------------
// Kernel: deterministic reduce of KV partials (fixed ascending order)
// ---------------------------------------------------------------------------
__global__ __launch_bounds__(256)
void k_kvr()
{
    const int bh = blockIdx.x;
    for (int i = threadIdx.x; i < 65 * 64; i += 256) {
        float s = 0.f;
#pragma unroll
        for (int ns = 0; ns < NSPLIT; ns++)
            s += g_kvp[((size_t)bh * NSPLIT + ns) * 65 * 64 + i];
        g_kv[(size_t)bh * 65 * 64 + i] = s;
    }
}

// ---------------------------------------------------------------------------
// Kernel: fold w_o into kv -> bf16 hi/lo M matrices
//   M_b[c, h*64+d] = sum_e w_o[c, h*64+e] * kv[e,d]
// ---------------------------------------------------------------------------
__global__ __launch_bounds__(256)
void k_fold(const float* __restrict__ w_o)
{
    __shared__ float kvs[64][65];
    __shared__ float ws[4][64];

    const int bh = blockIdx.x;
    const int b = bh >> 3, h = bh & 7;
    const int tid = threadIdx.x;

    for (int i = tid; i < 64 * 64; i += 256)
        kvs[i >> 6][i & 63] = g_kv[(size_t)bh * 65 * 64 + i];

    const int d  = tid & 63;
    const int cl = tid >> 6;

    for (int cc = 0; cc < 128; cc++) {
        __syncthreads();
        ws[tid >> 6][tid & 63] =
            w_o[(size_t)(cc * 4 + (tid >> 6)) * 512 + h * 64 + (tid & 63)];
        __syncthreads();
        float accv = 0.f;
#pragma unroll
        for (int e = 0; e < 64; e++) accv += ws[cl][e] * kvs[e][d];
        int c = cc * 4 + cl;
        size_t idx = ((size_t)b * 512 + c) * 512 + h * 64 + d;
        __nv_bfloat16 hi = __float2bfloat16(accv);
        s_Mhi[idx] = hi;
        s_Mlo[idx] = __float2bfloat16(accv - __bfloat162float(hi));
    }
}

// ---------------------------------------------------------------------------
// Kernel: denominator + scaled q^T in bf16 hi/lo:
//   den[h,n] = sum_d kv[64,d]*q[h*64+d, n];  qT[b][n][h*64+d] = q/(den+eps)
// ---------------------------------------------------------------------------
__global__ __launch_bounds__(256)
void k_scale()
{
    __shared__ float r[64];
    const int bh = blockIdx.x;
    const int n  = blockIdx.y * 256 + threadIdx.x;

    if (threadIdx.x < 64)
        r[threadIdx.x] = g_kv[(size_t)bh * 65 * 64 + 64 * 64 + threadIdx.x];
    __syncthreads();

    const float* qcol = g_q + (size_t)bh * 64 * N_ + n;
    float qv[64];
    float den = 0.f;
#pragma unroll
    for (int dd = 0; dd < 64; dd++) {
        qv[dd] = qcol[(size_t)dd * N_];
        den += r[dd] * qv[dd];
    }
    const float inv = 1.0f / (den + EPSF);

    const int b = bh >> 3, h = bh & 7;
    const size_t o = ((size_t)b * N_ + n) * C_ + h * 64;

#pragma unroll
    for (int g = 0; g < 8; g++) {
        uint32_t hw[4], lw[4];
#pragma unroll
        for (int j = 0; j < 4; j++) {
            float v0 = qv[g * 8 + 2 * j] * inv;
            float v1 = qv[g * 8 + 2 * j + 1] * inv;
            __nv_bfloat16 h0 = __float2bfloat16(v0);
            __nv_bfloat16 h1 = __float2bfloat16(v1);
            hw[j] = (uint32_t)__bfloat16_as_ushort(h0) |
                    ((uint32_t)__bfloat16_as_ushort(h1) << 16);
            lw[j] = pack_bf2(v0 - __bfloat162float(h0), v1 - __bfloat162float(h1));
        }
        *reinterpret_cast<uint4*>(s_qT_hi + o + g * 8) = make_uint4(hw[0], hw[1], hw[2], hw[3]);
        *reinterpret_cast<uint4*>(s_qT_lo + o + g * 8) = make_uint4(lw[0], lw[1], lw[2], lw[3]);
    }
}

// ---------------------------------------------------------------------------
extern "C" void kernel_launch(void* const* d_in, const int* in_sizes, int n_in,
                              void* d_out, int out_size)
{
    const float* x    = (const float*)d_in[0];
    const float* pos  = (const float*)d_in[1];
    const float* w_qk = (const float*)d_in[2];
    const float* w_v  = (const float*)d_in[3];
    const float* w_o  = (const float*)d_in[4];
    float* out = (float*)d_out;

    cudaFuncSetAttribute(k_gemm<0>, cudaFuncAttributeMaxDynamicSharedMemorySize, GSMEM_BYTES);
    cudaFuncSetAttribute(k_gemm<1>, cudaFuncAttributeMaxDynamicSharedMemorySize, GSMEM_BYTES);

    k_convw<<<(1536 * 512) / 256, 256>>>(w_qk, w_v);

    dim3 gp(N_ / 32, C_ / 32, B_);
    k_prep<<<gp, 256>>>(x, pos);

    dim3 g0(12, 32, B_);                       // (bm, bn, b)
    k_gemm<0><<<g0, 256, GSMEM_BYTES>>>(nullptr);

    dim3 gkv(B_ * NH, NSPLIT);
    k_kvp<<<gkv, 256>>>();
    k_kvr<<<B_ * NH, 256>>>();

    k_fold<<<B_ * NH, 256>>>(w_o);

    dim3 gs(B_ * NH, 16);
    k_scale<<<gs, 256>>>();

    dim3 g1(4, 32, B_);
    k_gemm<1><<<g1, 256, GSMEM_BYTES>>>(out);
}

// round 14
// speedup vs baseline: 2.2414x; 1.0023x over previous
#include <cuda_runtime.h>
#include <cuda_bf16.h>
#include <cstdint>
#include <cstddef>

// Problem constants
#define B_  16
#define C_  512
#define N_  4096
#define NH  8
#define HD  64
#define EPSF 1e-6f
#define NSPLIT 16

// ---------------------------------------------------------------------------
// Scratch (device globals: allocation-free rule)
// ---------------------------------------------------------------------------
__device__ float g_q [B_ * C_ * N_];        // relu(q) fp32 (consumed by k_scale)
__device__ float g_k [B_ * C_ * N_];        // relu(k)
__device__ float g_v [B_ * C_ * N_];        // v
__device__ float g_kv [B_ * NH * 65 * HD];           // per (b,h): [65][64]
__device__ float g_kvp[B_ * NH * NSPLIT * 65 * HD];  // split-N partials

// bf16 split operands
__device__ __nv_bfloat16 s_Ahi[1536 * 512]; // [w_qk ; w_v] rows, K-major
__device__ __nv_bfloat16 s_Alo[1536 * 512];
__device__ __nv_bfloat16 s_Bxp_hi[(size_t)B_ * N_ * C_];  // (x+pos)^T : [b][n][k]
__device__ __nv_bfloat16 s_Bxp_lo[(size_t)B_ * N_ * C_];
__device__ __nv_bfloat16 s_Bx_hi [(size_t)B_ * N_ * C_];  // x^T : [b][n][k]
__device__ __nv_bfloat16 s_Bx_lo [(size_t)B_ * N_ * C_];
__device__ __nv_bfloat16 s_qT_hi [(size_t)B_ * N_ * C_];  // scaled q^T : [b][n][c]
__device__ __nv_bfloat16 s_qT_lo [(size_t)B_ * N_ * C_];
__device__ __nv_bfloat16 s_Mhi[B_ * C_ * C_];             // folded w_o@kv per batch
__device__ __nv_bfloat16 s_Mlo[B_ * C_ * C_];

// ---------------------------------------------------------------------------
// mma.sync + cp.async helpers (sm_80 baseline PTX — compiles at compute_103)
// ---------------------------------------------------------------------------
__device__ __forceinline__ uint32_t smem_u32(const void* p) {
    uint32_t a;
    asm("{ .reg .u64 t; cvta.to.shared.u64 t, %1; cvt.u32.u64 %0, t; }" : "=r"(a) : "l"(p));
    return a;
}
__device__ __forceinline__ void ldsm4(uint32_t* r, uint32_t addr) {
    asm volatile("ldmatrix.sync.aligned.m8n8.x4.shared.b16 {%0,%1,%2,%3}, [%4];"
                 : "=r"(r[0]), "=r"(r[1]), "=r"(r[2]), "=r"(r[3]) : "r"(addr));
}
__device__ __forceinline__ void mma16816(float* c, const uint32_t* a, const uint32_t* b) {
    asm volatile(
        "mma.sync.aligned.m16n8k16.row.col.f32.bf16.bf16.f32 "
        "{%0,%1,%2,%3}, {%4,%5,%6,%7}, {%8,%9}, {%0,%1,%2,%3};"
        : "+f"(c[0]), "+f"(c[1]), "+f"(c[2]), "+f"(c[3])
        : "r"(a[0]), "r"(a[1]), "r"(a[2]), "r"(a[3]), "r"(b[0]), "r"(b[1]));
}
__device__ __forceinline__ void cp_async16(uint32_t saddr, const void* gptr) {
    asm volatile("cp.async.cg.shared.global [%0], [%1], 16;"
                 :: "r"(saddr), "l"(gptr) : "memory");
}
#define CP_COMMIT()  asm volatile("cp.async.commit_group;" ::: "memory")
#define CP_WAIT(nn)  asm volatile("cp.async.wait_group %0;" :: "n"(nn) : "memory")

__device__ __forceinline__ uint32_t pack_bf2(float a, float b) {
    __nv_bfloat16 ha = __float2bfloat16(a), hb = __float2bfloat16(b);
    return (uint32_t)__bfloat16_as_ushort(ha) |
           ((uint32_t)__bfloat16_as_ushort(hb) << 16);
}

// ---------------------------------------------------------------------------
// Kernel: weight conversion fp32 -> bf16 hi/lo  (1536x512)
// ---------------------------------------------------------------------------
__global__ void k_convw(const float* __restrict__ w_qk, const float* __restrict__ w_v)
{
    int idx = blockIdx.x * 256 + threadIdx.x;          // 0 .. 1536*512-1
    float v = (idx < 1024 * 512) ? w_qk[idx] : w_v[idx - 1024 * 512];
    __nv_bfloat16 h = __float2bfloat16(v);
    s_Ahi[idx] = h;
    s_Alo[idx] = __float2bfloat16(v - __bfloat162float(h));
}

// ---------------------------------------------------------------------------
// Kernel: transpose + convert x / (x+pos)  ->  [b][n][k] bf16 hi/lo
// ---------------------------------------------------------------------------
__global__ __launch_bounds__(256)
void k_prep(const float* __restrict__ x, const float* __restrict__ pos)
{
    __shared__ float sx[32][33];
    __shared__ float sp[32][33];
    const int b  = blockIdx.z;
    const int k0 = blockIdx.y * 32;
    const int n0 = blockIdx.x * 32;
    const int c  = threadIdx.x & 31;
    const int r0 = threadIdx.x >> 5;   // 0..7

#pragma unroll
    for (int i = 0; i < 4; i++) {
        int r = r0 + 8 * i;
        size_t off = ((size_t)b * C_ + k0 + r) * N_ + n0 + c;
        float xv = x[off];
        sx[r][c] = xv;
        sp[r][c] = xv + pos[off];
    }
    __syncthreads();
#pragma unroll
    for (int i = 0; i < 4; i++) {
        int r = r0 + 8 * i;                       // n within tile
        float vx = sx[c][r];
        float vp = sp[c][r];
        size_t o = ((size_t)b * N_ + n0 + r) * C_ + k0 + c;
        __nv_bfloat16 hp = __float2bfloat16(vp);
        __nv_bfloat16 hx = __float2bfloat16(vx);
        s_Bxp_hi[o] = hp;
        s_Bxp_lo[o] = __float2bfloat16(vp - __bfloat162float(hp));
        s_Bx_hi[o]  = hx;
        s_Bx_lo[o]  = __float2bfloat16(vx - __bfloat162float(hx));
    }
}

// ---------------------------------------------------------------------------
// HMMA GEMM (bf16x3 emulated fp32): D[m][n] = sum_k A[m][k] * B[n][k]
//   Block tile 128x128, K-chunk 64, 8 warps (warp tile 32x64),
//   cp.async double-buffered over K-chunks.
//   MODE 0: QKV  — A = s_Ahi/lo (1536 rows), B = Bxp (bm<8) or Bx,
//                  out -> g_q/g_k/g_v (relu on q,k)
//   MODE 1: final — A = s_Mhi/lo per batch, B = s_qT, out -> d_out
// grid: (bm, bn, b); block 256 threads.
// ---------------------------------------------------------------------------
#define TSTRIDE 72                 // smem row stride (elems), conflict-free for ldmatrix
#define TILE_BYTES_SM (128 * TSTRIDE * 2)       // 18432
#define BUF_BYTES (4 * TILE_BYTES_SM)           // 73728
#define GSMEM_BYTES (2 * BUF_BYTES)             // 147456

__device__ __forceinline__ void issue_chunk(const __nv_bfloat16* const* srcs,
                                            int kc, uint32_t sbase, int tid)
{
#pragma unroll
    for (int buf = 0; buf < 4; buf++) {
        const __nv_bfloat16* bp = srcs[buf] + kc * 64;
        uint32_t tbase = sbase + buf * TILE_BYTES_SM;
#pragma unroll
        for (int it = 0; it < 4; it++) {
            int u = it * 256 + tid;          // 0..1023
            int row = u >> 3, c8 = u & 7;    // col = c8*8
            cp_async16(tbase + (uint32_t)(row * TSTRIDE + c8 * 8) * 2,
                       bp + (size_t)row * 512 + c8 * 8);
        }
    }
}

template <int MODE>
__global__ __launch_bounds__(256)
void k_gemm(float* __restrict__ out)
{
    extern __shared__ __nv_bfloat16 smem[];   // 2 buffers x 4 tiles
    const int tid = threadIdx.x;
    const int lane = tid & 31;
    const int wid  = tid >> 5;
    const int warp_m = wid & 3;          // 0..3  (m-tile of 32)
    const int warp_n = wid >> 2;         // 0..1  (n-tile of 64)
    const int bm = blockIdx.x, bn = blockIdx.y, b = blockIdx.z;

    // operand base pointers (row-major [rows][512])
    const __nv_bfloat16 *pAhi, *pAlo, *pBhi, *pBlo;
    if (MODE == 0) {
        pAhi = s_Ahi + (size_t)bm * 128 * 512;
        pAlo = s_Alo + (size_t)bm * 128 * 512;
        size_t bo = ((size_t)b * N_ + (size_t)bn * 128) * 512;
        if (bm < 8) { pBhi = s_Bxp_hi + bo; pBlo = s_Bxp_lo + bo; }
        else        { pBhi = s_Bx_hi  + bo; pBlo = s_Bx_lo  + bo; }
    } else {
        pAhi = s_Mhi + ((size_t)b * 512 + (size_t)bm * 128) * 512;
        pAlo = s_Mlo + ((size_t)b * 512 + (size_t)bm * 128) * 512;
        size_t bo = ((size_t)b * N_ + (size_t)bn * 128) * 512;
        pBhi = s_qT_hi + bo;
        pBlo = s_qT_lo + bo;
    }
    const __nv_bfloat16* srcs[4] = { pAhi, pAlo, pBhi, pBlo };

    const uint32_t sb = smem_u32(smem);

    // ldmatrix per-lane address components
    const uint32_t a_row   = warp_m * 32 + (lane & 15);       // + mi*16
    const uint32_t a_csel  = (lane >> 4) * 8;                 // k half
    const uint32_t b_row   = warp_n * 64 + (lane & 7) + ((lane >> 4) & 1) * 8; // + nj*16
    const uint32_t b_csel  = ((lane >> 3) & 1) * 8;

    float acc[2][8][4];
#pragma unroll
    for (int i = 0; i < 2; i++)
#pragma unroll
        for (int j = 0; j < 8; j++)
#pragma unroll
            for (int r = 0; r < 4; r++) acc[i][j][r] = 0.f;

    // prologue: prefetch chunk 0
    issue_chunk(srcs, 0, sb, tid);
    CP_COMMIT();

    for (int kc = 0; kc < 8; kc++) {
        // prefetch next chunk into alternate buffer
        if (kc + 1 < 8) {
            issue_chunk(srcs, kc + 1, sb + ((kc + 1) & 1) * BUF_BYTES, tid);
            CP_COMMIT();
            CP_WAIT(1);
        } else {
            CP_WAIT(0);
        }
        __syncthreads();

        const uint32_t cbase = sb + (kc & 1) * BUF_BYTES;
        const uint32_t sAhi = cbase;
        const uint32_t sAlo = cbase + TILE_BYTES_SM;
        const uint32_t sBhi = cbase + 2 * TILE_BYTES_SM;
        const uint32_t sBlo = cbase + 3 * TILE_BYTES_SM;

        // ---- 4 K-steps of 16 ----
#pragma unroll
        for (int ks = 0; ks < 4; ks++) {
            const uint32_t kcol = ks * 16;
            uint32_t ah[2][4], al[2][4];
#pragma unroll
            for (int mi = 0; mi < 2; mi++) {
                uint32_t ro = (a_row + mi * 16) * TSTRIDE + kcol + a_csel;
                ldsm4(ah[mi], sAhi + ro * 2);
                ldsm4(al[mi], sAlo + ro * 2);
            }
            uint32_t bh[4][4], bl[4][4];       // each covers n-tiles 2nj, 2nj+1
#pragma unroll
            for (int nj = 0; nj < 4; nj++) {
                uint32_t ro = (b_row + nj * 16) * TSTRIDE + kcol + b_csel;
                ldsm4(bh[nj], sBhi + ro * 2);
                ldsm4(bl[nj], sBlo + ro * 2);
            }
#pragma unroll
            for (int mi = 0; mi < 2; mi++)
#pragma unroll
                for (int nj = 0; nj < 4; nj++) {
                    mma16816(acc[mi][2 * nj    ], ah[mi], &bh[nj][0]);
                    mma16816(acc[mi][2 * nj + 1], ah[mi], &bh[nj][2]);
                    mma16816(acc[mi][2 * nj    ], ah[mi], &bl[nj][0]);
                    mma16816(acc[mi][2 * nj + 1], ah[mi], &bl[nj][2]);
                    mma16816(acc[mi][2 * nj    ], al[mi], &bh[nj][0]);
                    mma16816(acc[mi][2 * nj + 1], al[mi], &bh[nj][2]);
                }
        }
        __syncthreads();   // tile consumed — safe for the prefetch after next
    }

    // ---- epilogue ----
    float* base;
    int roff;
    bool relu = false;
    if (MODE == 0) {
        if (bm < 4)      { base = g_q; roff = bm * 128;        relu = true; }
        else if (bm < 8) { base = g_k; roff = (bm - 4) * 128;  relu = true; }
        else             { base = g_v; roff = (bm - 8) * 128; }
        base += (size_t)b * C_ * N_;
    } else {
        base = out + (size_t)b * C_ * N_;
        roff = bm * 128;
    }

    const int mrow0 = roff + warp_m * 32 + (lane >> 2);
    const int ncol0 = bn * 128 + warp_n * 64 + (lane & 3) * 2;
#pragma unroll
    for (int mi = 0; mi < 2; mi++) {
#pragma unroll
        for (int nj = 0; nj < 8; nj++) {
            int cc = ncol0 + nj * 8;
            float2 v0 = make_float2(acc[mi][nj][0], acc[mi][nj][1]);
            float2 v1 = make_float2(acc[mi][nj][2], acc[mi][nj][3]);
            if (relu) {
                v0.x = fmaxf(v0.x, 0.f); v0.y = fmaxf(v0.y, 0.f);
                v1.x = fmaxf(v1.x, 0.f); v1.y = fmaxf(v1.y, 0.f);
            }
            *reinterpret_cast<float2*>(base + (size_t)(mrow0 + mi * 16    ) * N_ + cc) = v0;
            *reinterpret_cast<float2*>(base + (size_t)(mrow0 + mi * 16 + 8) * N_ + cc) = v1;
        }
    }
}

// ---------------------------------------------------------------------------
// Kernel: split-N partial KV: kvp[bh][ns][e][d] = sum_{n in slice} v_pad[e,n]*k[d,n]
//   grid (128, NSPLIT); block 256 as (16,16).
//   Vectorized: float4 along n (8x LDS.128 -> 64 FFMA per step).
//   Row pad 68 floats => stride 272B => conflict-free LDS.128 phases.
// ---------------------------------------------------------------------------
__global__ __launch_bounds__(256)
void k_kvp()
{
    __shared__ float Ks[64][68];
    __shared__ float Vs[64][68];

    const int bh  = blockIdx.x;
    const int ns  = blockIdx.y;
    const int tid = threadIdx.x;
    const int tx = tid & 15, ty = tid >> 4;

    const float* Kg = g_k + (size_t)bh * 64 * N_;
    const float* Vg = g_v + (size_t)bh * 64 * N_;

    float acc[4][4];
    float acco[4];
#pragma unroll
    for (int i = 0; i < 4; i++) {
        acco[i] = 0.f;
#pragma unroll
        for (int j = 0; j < 4; j++) acc[i][j] = 0.f;
    }

    const int lr = tid >> 4;          // 0..15
    const int lc = (tid & 15) * 4;    // 0..60
    const int nbeg = ns * (N_ / NSPLIT);
    const int nend = nbeg + (N_ / NSPLIT);

    for (int n0 = nbeg; n0 < nend; n0 += 64) {
        __syncthreads();
#pragma unroll
        for (int rr = 0; rr < 4; rr++) {
            int row = lr + 16 * rr;
            float4 kq = *reinterpret_cast<const float4*>(Kg + (size_t)row * N_ + n0 + lc);
            float4 vq = *reinterpret_cast<const float4*>(Vg + (size_t)row * N_ + n0 + lc);
            *reinterpret_cast<float4*>(&Ks[row][lc]) = kq;
            *reinterpret_cast<float4*>(&Vs[row][lc]) = vq;
        }
        __syncthreads();

#pragma unroll
        for (int nn = 0; nn < 64; nn += 4) {
            float4 kk[4], vv[4];
#pragma unroll
            for (int j = 0; j < 4; j++)
                kk[j] = *reinterpret_cast<const float4*>(&Ks[tx + 16 * j][nn]);
#pragma unroll
            for (int i = 0; i < 4; i++)
                vv[i] = *reinterpret_cast<const float4*>(&Vs[ty + 16 * i][nn]);
#pragma unroll
            for (int i = 0; i < 4; i++)
#pragma unroll
                for (int j = 0; j < 4; j++) {
                    acc[i][j] += vv[i].x * kk[j].x;
                    acc[i][j] += vv[i].y * kk[j].y;
                    acc[i][j] += vv[i].z * kk[j].z;
                    acc[i][j] += vv[i].w * kk[j].w;
                }
            if (ty == 0) {
#pragma unroll
                for (int j = 0; j < 4; j++)
                    acco[j] += (kk[j].x + kk[j].y) + (kk[j].z + kk[j].w);
            }
        }
    }

    float* kvb = g_kvp + ((size_t)bh * NSPLIT + ns) * 65 * 64;
#pragma unroll
    for (int i = 0; i < 4; i++)
#pragma unroll
        for (int j = 0; j < 4; j++)
            kvb[(ty + 16 * i) * 64 + tx + 16 * j] = acc[i][j];
    if (ty == 0) {
#pragma unroll
        for (int j = 0; j < 4; j++) kvb[64 * 64 + tx + 16 * j] = acco[j];
    }
}

// ---------------------------------------------------------------------------
// Kernel: deterministic reduce of KV partials (fixed ascending order)
// ---------------------------------------------------------------------------
__global__ __launch_bounds__(256)
void k_kvr()
{
    const int bh = blockIdx.x;
    for (int i = threadIdx.x; i < 65 * 64; i += 256) {
        float s = 0.f;
#pragma unroll
        for (int ns = 0; ns < NSPLIT; ns++)
            s += g_kvp[((size_t)bh * NSPLIT + ns) * 65 * 64 + i];
        g_kv[(size_t)bh * 65 * 64 + i] = s;
    }
}

// ---------------------------------------------------------------------------
// Kernel: fold w_o into kv -> bf16 hi/lo M matrices
//   M_b[c, h*64+d] = sum_e w_o[c, h*64+e] * kv[e,d]
// ---------------------------------------------------------------------------
__global__ __launch_bounds__(256)
void k_fold(const float* __restrict__ w_o)
{
    __shared__ float kvs[64][65];
    __shared__ float ws[4][64];

    const int bh = blockIdx.x;
    const int b = bh >> 3, h = bh & 7;
    const int tid = threadIdx.x;

    for (int i = tid; i < 64 * 64; i += 256)
        kvs[i >> 6][i & 63] = g_kv[(size_t)bh * 65 * 64 + i];

    const int d  = tid & 63;
    const int cl = tid >> 6;

    for (int cc = 0; cc < 128; cc++) {
        __syncthreads();
        ws[tid >> 6][tid & 63] =
            w_o[(size_t)(cc * 4 + (tid >> 6)) * 512 + h * 64 + (tid & 63)];
        __syncthreads();
        float accv = 0.f;
#pragma unroll
        for (int e = 0; e < 64; e++) accv += ws[cl][e] * kvs[e][d];
        int c = cc * 4 + cl;
        size_t idx = ((size_t)b * 512 + c) * 512 + h * 64 + d;
        __nv_bfloat16 hi = __float2bfloat16(accv);
        s_Mhi[idx] = hi;
        s_Mlo[idx] = __float2bfloat16(accv - __bfloat162float(hi));
    }
}

// ---------------------------------------------------------------------------
// Kernel: denominator + scaled q^T in bf16 hi/lo:
//   den[h,n] = sum_d kv[64,d]*q[h*64+d, n];  qT[b][n][h*64+d] = q/(den+eps)
// ---------------------------------------------------------------------------
__global__ __launch_bounds__(256)
void k_scale()
{
    __shared__ float r[64];
    const int bh = blockIdx.x;
    const int n  = blockIdx.y * 256 + threadIdx.x;

    if (threadIdx.x < 64)
        r[threadIdx.x] = g_kv[(size_t)bh * 65 * 64 + 64 * 64 + threadIdx.x];
    __syncthreads();

    const float* qcol = g_q + (size_t)bh * 64 * N_ + n;
    float qv[64];
    float den = 0.f;
#pragma unroll
    for (int dd = 0; dd < 64; dd++) {
        qv[dd] = qcol[(size_t)dd * N_];
        den += r[dd] * qv[dd];
    }
    const float inv = 1.0f / (den + EPSF);

    const int b = bh >> 3, h = bh & 7;
    const size_t o = ((size_t)b * N_ + n) * C_ + h * 64;

#pragma unroll
    for (int g = 0; g < 8; g++) {
        uint32_t hw[4], lw[4];
#pragma unroll
        for (int j = 0; j < 4; j++) {
            float v0 = qv[g * 8 + 2 * j] * inv;
            float v1 = qv[g * 8 + 2 * j + 1] * inv;
            __nv_bfloat16 h0 = __float2bfloat16(v0);
            __nv_bfloat16 h1 = __float2bfloat16(v1);
            hw[j] = (uint32_t)__bfloat16_as_ushort(h0) |
                    ((uint32_t)__bfloat16_as_ushort(h1) << 16);
            lw[j] = pack_bf2(v0 - __bfloat162float(h0), v1 - __bfloat162float(h1));
        }
        *reinterpret_cast<uint4*>(s_qT_hi + o + g * 8) = make_uint4(hw[0], hw[1], hw[2], hw[3]);
        *reinterpret_cast<uint4*>(s_qT_lo + o + g * 8) = make_uint4(lw[0], lw[1], lw[2], lw[3]);
    }
}

// ---------------------------------------------------------------------------
extern "C" void kernel_launch(void* const* d_in, const int* in_sizes, int n_in,
                              void* d_out, int out_size)
{
    const float* x    = (const float*)d_in[0];
    const float* pos  = (const float*)d_in[1];
    const float* w_qk = (const float*)d_in[2];
    const float* w_v  = (const float*)d_in[3];
    const float* w_o  = (const float*)d_in[4];
    float* out = (float*)d_out;

    cudaFuncSetAttribute(k_gemm<0>, cudaFuncAttributeMaxDynamicSharedMemorySize, GSMEM_BYTES);
    cudaFuncSetAttribute(k_gemm<1>, cudaFuncAttributeMaxDynamicSharedMemorySize, GSMEM_BYTES);

    k_convw<<<(1536 * 512) / 256, 256>>>(w_qk, w_v);

    dim3 gp(N_ / 32, C_ / 32, B_);
    k_prep<<<gp, 256>>>(x, pos);

    dim3 g0(12, 32, B_);                       // (bm, bn, b)
    k_gemm<0><<<g0, 256, GSMEM_BYTES>>>(nullptr);

    dim3 gkv(B_ * NH, NSPLIT);
    k_kvp<<<gkv, 256>>>();
    k_kvr<<<B_ * NH, 256>>>();

    k_fold<<<B_ * NH, 256>>>(w_o);

    dim3 gs(B_ * NH, 16);
    k_scale<<<gs, 256>>>();

    dim3 g1(4, 32, B_);
    k_gemm<1><<<g1, 256, GSMEM_BYTES>>>(out);
}